// round 12
// baseline (speedup 1.0000x reference)
#include <cuda_runtime.h>
#include <float.h>

#define H_IN   161
#define W_IN   161
#define C      128
#define H_OUT  641
#define W_OUT  641
#define NPIX   (H_OUT * W_OUT)
#define NEGV   (-1000000000.0f)
#define LOG2E  1.4426950408889634f

#define TPB      224     // 56 quads * 4 channel-quarters
#define OCC      6
#define STRIPQ   56      // quads per strip (strips: 56, 56, 49)
#define NCOLS    57      // max columns stored (56 quads + boundary)
#define CSTRIDE  144     // column stride in floats (mod 32 == 16)
#define QSTRIDE  36      // quarter stride in floats (mod 32 == 4, 16B aligned)
#define NITEMS   (H_OUT * 3)

typedef unsigned long long ull;

#define EX2(dst, src) asm("ex2.approx.f32 %0, %1;" : "=f"(dst) : "f"(src))

__device__ __forceinline__ void f2x2_unpack(ull v, float& lo, float& hi) {
    asm("mov.b64 {%0, %1}, %2;" : "=f"(lo), "=f"(hi) : "l"(v));
}

// Epilogue: within-group channel of the per-pixel max in EXP domain.
// Bit-identical recomputation of the main-loop t chain (same op order);
// first occurrence on ties (scan high->low, overwrite).
__device__ __forceinline__ int scan_group(const float4* pa, const float4* pb,
                                          int bg, float m, int p) {
    float4 A = pa[bg];
    float4 B = pb[bg];
    float q0 = fmaf(B.x, 0.25f, A.x * -0.25f);
    float q1 = fmaf(B.y, 0.25f, A.y * -0.25f);
    float q2 = fmaf(B.z, 0.25f, A.z * -0.25f);
    float q3 = fmaf(B.w, 0.25f, A.w * -0.25f);
    float t0, t1, t2, t3, r0, r1, r2, r3;
    EX2(t0, A.x); EX2(t1, A.y); EX2(t2, A.z); EX2(t3, A.w);
    EX2(r0, q0);  EX2(r1, q1);  EX2(r2, q2);  EX2(r3, q3);
    for (int k = 0; k < p; ++k) { t0 *= r0; t1 *= r1; t2 *= r2; t3 *= r3; }
    int r = 3;
    if (t2 == m) r = 2;
    if (t1 == m) r = 1;
    if (t0 == m) r = 0;
    return 4 * bg + r;
}

// ---------------------------------------------------------------------------
// Single fused persistent kernel.
//  - classify phase (per block, redundant, L2-resident input)
//  - persistent loop over 1923 (row, strip) items:
//      fill: y-lerp (log2e-prescaled) into padded SMEM
//      fast path: quad scheme, 2 EX2/channel feed softmax sums AND exp-domain
//                 maxes for 4 sub-pixels; quad-shfl combine; argmax re-scan.
// ---------------------------------------------------------------------------
__global__ void __launch_bounds__(TPB, OCC)
fused_kernel(const float* __restrict__ in, const float* __restrict__ probs,
             float* __restrict__ out) {
    __shared__ float sbuf[NCOLS * CSTRIDE];   // 32832 B
    __shared__ float sbias[128];
    __shared__ int   ssem[128];
    __shared__ int   smaskid[128];
    __shared__ unsigned swmask[4];
    __shared__ unsigned char sdetsh[128];
    __shared__ int   sflags;

    const int tid  = threadIdx.x;
    const int lane = tid & 31;

    // ================= CLASSIFY (once per block) =================
    if (tid < 128) {
        const float* row = probs + tid * 134;
        float best = row[0];
        int bi = 0;
        #pragma unroll 4
        for (int c = 1; c < 133; ++c) {
            float v = row[c];
            if (v > best) { best = v; bi = c; }   // strict >: first occurrence
        }
        ssem[tid]   = bi;
        sdetsh[tid] = (best >= 0.7f) ? 1 : 0;
    }
    __syncthreads();
    if (tid < 128) {
        unsigned b = __ballot_sync(0xffffffffu, sdetsh[tid] != 0);
        if (lane == 0) swmask[tid >> 5] = b;
    }
    __syncthreads();
    if (tid < 128) {
        unsigned b = swmask[tid >> 5];
        int cnt = __popc(b & (0xffffffffu >> (31 - lane)));
        for (int k = 0; k < (tid >> 5); ++k) cnt += __popc(swmask[k]);
        smaskid[tid] = cnt - 1;
        sbias[tid]   = ((b >> lane) & 1u) ? 0.0f : NEGV;
    }
    if (tid == 0) {
        int tot = __popc(swmask[0]) + __popc(swmask[1]) +
                  __popc(swmask[2]) + __popc(swmask[3]);
        sflags = ((tot > 0) ? 1 : 0) | ((tot == 128) ? 2 : 0);
    }
    __syncthreads();
    const int hasdet = sflags & 1;
    const int alldet = sflags & 2;

    // ================= PERSISTENT ITEM LOOP =================
    for (int w = blockIdx.x; w < NITEMS; w += gridDim.x) {
        const int y     = w / 3;
        const int strip = w - y * 3;
        const int cb    = strip * STRIPQ;                 // 0 / 56 / 112
        const int nq    = (strip == 2) ? 49 : 56;         // quads this item
        const int nc    = (strip == 2) ? 49 : 57;         // columns to load

        const int y0 = y >> 2;
        const int y1 = min(y0 + 1, H_IN - 1);
        const float wy = (float)(y & 3) * 0.25f;
        const float w1 = wy * LOG2E;
        const float w0 = (1.0f - wy) * LOG2E;

        // ---- fill: y-lerp (log2e-prescaled) into padded SMEM ----
        {
            const float4* r0 = (const float4*)(in + ((size_t)y0 * W_IN + cb) * C);
            const float4* r1 = (const float4*)(in + ((size_t)y1 * W_IN + cb) * C);
            const int nv = nc * 32;   // float4 count
            if ((y & 3) == 0) {
                #pragma unroll 4
                for (int i = tid; i < nv; i += TPB) {
                    float4 a = r0[i];
                    float* dst = sbuf + (i >> 5) * CSTRIDE
                                      + ((i & 31) >> 3) * QSTRIDE + (i & 7) * 4;
                    *(float4*)dst = make_float4(a.x * w0, a.y * w0,
                                                a.z * w0, a.w * w0);
                }
            } else {
                #pragma unroll 4
                for (int i = tid; i < nv; i += TPB) {
                    float4 a = r0[i], b = r1[i];
                    float* dst = sbuf + (i >> 5) * CSTRIDE
                                      + ((i & 31) >> 3) * QSTRIDE + (i & 7) * 4;
                    *(float4*)dst = make_float4(a.x * w0 + b.x * w1,
                                                a.y * w0 + b.y * w1,
                                                a.z * w0 + b.z * w1,
                                                a.w * w0 + b.w * w1);
                }
            }
        }
        __syncthreads();

        if (alldet) {
            // ================= FAST PATH =================
            const int qrel    = tid >> 2;          // quad within item
            const int quarter = tid & 3;           // channel quarter
            if (qrel < nq) {
                const int qd  = cb + qrel;         // input column / quad id
                const int x1c = min(qrel + 1, nc - 1);
                const float4* pa = (const float4*)(sbuf + qrel * CSTRIDE + quarter * QSTRIDE);
                const float4* pb = (const float4*)(sbuf + x1c  * CSTRIDE + quarter * QSTRIDE);
                const unsigned pm = 0xFu << (lane & 28);

                float s0 = 0.f, s1 = 0.f, s2 = 0.f, s3 = 0.f;
                float m0 = 0.f, m1 = 0.f, m2 = 0.f, m3 = 0.f;  // exp-domain maxes
                int   bg0 = 0, bg1 = 0, bg2 = 0, bg3 = 0;

                #pragma unroll
                for (int g = 0; g < 8; ++g) {
                    float4 A = pa[g];
                    float4 B = pb[g];
                    float q0 = fmaf(B.x, 0.25f, A.x * -0.25f);
                    float q1 = fmaf(B.y, 0.25f, A.y * -0.25f);
                    float q2 = fmaf(B.z, 0.25f, A.z * -0.25f);
                    float q3 = fmaf(B.w, 0.25f, A.w * -0.25f);

                    float e0, e1, e2, e3, r0, r1, r2, r3;
                    EX2(e0, A.x); EX2(e1, A.y); EX2(e2, A.z); EX2(e3, A.w);
                    EX2(r0, q0);  EX2(r1, q1);  EX2(r2, q2);  EX2(r3, q3);

                    // pixel 0
                    float gm0 = fmaxf(fmaxf(e0, e1), fmaxf(e2, e3));
                    s0 += e0; s0 += e1; s0 += e2; s0 += e3;
                    // pixel 1
                    float t10 = e0 * r0, t11 = e1 * r1, t12 = e2 * r2, t13 = e3 * r3;
                    float gm1 = fmaxf(fmaxf(t10, t11), fmaxf(t12, t13));
                    s1 += t10; s1 += t11; s1 += t12; s1 += t13;
                    // pixel 2
                    float t20 = t10 * r0, t21 = t11 * r1, t22 = t12 * r2, t23 = t13 * r3;
                    float gm2 = fmaxf(fmaxf(t20, t21), fmaxf(t22, t23));
                    s2 += t20; s2 += t21; s2 += t22; s2 += t23;
                    // pixel 3
                    float t30 = t20 * r0, t31 = t21 * r1, t32 = t22 * r2, t33 = t23 * r3;
                    float gm3 = fmaxf(fmaxf(t30, t31), fmaxf(t32, t33));
                    s3 += t30; s3 += t31; s3 += t32; s3 += t33;

                    if (gm0 > m0) { m0 = gm0; bg0 = g; }  // strict >: earliest group
                    if (gm1 > m1) { m1 = gm1; bg1 = g; }
                    if (gm2 > m2) { m2 = gm2; bg2 = g; }
                    if (gm3 > m3) { m3 = gm3; bg3 = g; }
                }

                const int ch0 = quarter * 32;
                int bi0 = ch0 + scan_group(pa, pb, bg0, m0, 0);
                int bi1 = ch0 + scan_group(pa, pb, bg1, m1, 1);
                int bi2 = ch0 + scan_group(pa, pb, bg2, m2, 2);
                int bi3 = ch0 + scan_group(pa, pb, bg3, m3, 3);

                // combine across the 4 channel-quarters (quad shfl)
                #pragma unroll
                for (int off = 1; off <= 2; off <<= 1) {
                    s0 += __shfl_xor_sync(pm, s0, off);
                    s1 += __shfl_xor_sync(pm, s1, off);
                    s2 += __shfl_xor_sync(pm, s2, off);
                    s3 += __shfl_xor_sync(pm, s3, off);
                    float om; int oi;
                    om = __shfl_xor_sync(pm, m0, off); oi = __shfl_xor_sync(pm, bi0, off);
                    if (om > m0 || (om == m0 && oi < bi0)) { m0 = om; bi0 = oi; }
                    om = __shfl_xor_sync(pm, m1, off); oi = __shfl_xor_sync(pm, bi1, off);
                    if (om > m1 || (om == m1 && oi < bi1)) { m1 = om; bi1 = oi; }
                    om = __shfl_xor_sync(pm, m2, off); oi = __shfl_xor_sync(pm, bi2, off);
                    if (om > m2 || (om == m2 && oi < bi2)) { m2 = om; bi2 = oi; }
                    om = __shfl_xor_sync(pm, m3, off); oi = __shfl_xor_sync(pm, bi3, off);
                    if (om > m3 || (om == m3 && oi < bi3)) { m3 = om; bi3 = oi; }
                }

                if (quarter == 0) {
                    float sv[4]  = { s0, s1, s2, s3 };
                    float mv[4]  = { m0, m1, m2, m3 };
                    int   biv[4] = { bi0, bi1, bi2, bi3 };
                    #pragma unroll
                    for (int p4 = 0; p4 < 4; ++p4) {
                        const int px = 4 * qd + p4;
                        if (px < W_OUT) {
                            // pixel_conf > 0.4  <=>  s < 2.5 * m (m = 2^det_max)
                            const float cf = (sv[p4] < 2.5f * mv[p4]) ? 1.0f : 0.0f;
                            const int bi = biv[p4];
                            const int semI = ssem[bi];
                            const int p = y * W_OUT + px;
                            out[p]            = (float)(smaskid[bi] + 1);
                            out[NPIX + p]     = (float)semI;
                            out[2 * NPIX + p] = (semI < 80)  ? cf : 0.0f;
                            out[3 * NPIX + p] = (semI >= 80) ? cf : 0.0f;
                        }
                    }
                }
            }
        } else {
            // ================= GENERAL PATH (rare) =================
            const int px = 4 * cb + tid;
            if (tid < 4 * nq && px < W_OUT) {
                const int x0 = px >> 2;
                const int x1 = min(x0 + 1, W_IN - 1);
                const float wx   = (float)(px & 3) * 0.25f;
                const float omwx = 1.0f - wx;

                float fm = -FLT_MAX, bv = -FLT_MAX, s = 0.0f;
                int bi = 0;
                #pragma unroll
                for (int quarter = 0; quarter < 4; ++quarter) {
                    const ull* pa = (const ull*)(sbuf + (x0 - cb) * CSTRIDE + quarter * QSTRIDE);
                    const ull* pb = (const ull*)(sbuf + (x1 - cb) * CSTRIDE + quarter * QSTRIDE);
                    const ull* pg = (const ull*)(sbias + quarter * 32);
                    #pragma unroll 4
                    for (int c2 = 0; c2 < 16; ++c2) {
                        float a0, a1, b0, b1, gg0, gg1;
                        f2x2_unpack(pa[c2], a0, a1);
                        f2x2_unpack(pb[c2], b0, b1);
                        f2x2_unpack(pg[c2], gg0, gg1);
                        {
                            float v = a0 * omwx + b0 * wx;
                            fm = fmaxf(fm, v);
                            float mv = v + gg0;
                            if (mv > bv) { bv = mv; bi = quarter * 32 + 2 * c2; }
                            float e; EX2(e, mv); s += e;
                        }
                        {
                            float v = a1 * omwx + b1 * wx;
                            fm = fmaxf(fm, v);
                            float mv = v + gg1;
                            if (mv > bv) { bv = mv; bi = quarter * 32 + 2 * c2 + 1; }
                            float e; EX2(e, mv); s += e;
                        }
                    }
                }
                float eb; EX2(eb, bv);
                const float cf = (s < 2.5f * eb && fm == bv) ? 1.0f : 0.0f;

                float maskid, sem, thing, stuff;
                if (hasdet) {
                    const int semI = ssem[bi];
                    maskid = (float)(smaskid[bi] + 1);
                    sem    = (float)semI;
                    thing  = (semI < 80)  ? cf : 0.0f;
                    stuff  = (semI >= 80) ? cf : 0.0f;
                } else {
                    maskid = 1.0f; sem = 0.0f; thing = 0.0f; stuff = 0.0f;
                }
                const int p = y * W_OUT + px;
                out[p]            = maskid;
                out[NPIX + p]     = sem;
                out[2 * NPIX + p] = thing;
                out[3 * NPIX + p] = stuff;
            }
        }
        __syncthreads();   // sbuf reused next item
    }
}

// ---------------------------------------------------------------------------
extern "C" void kernel_launch(void* const* d_in, const int* in_sizes, int n_in,
                              void* d_out, int out_size) {
    const float* logits = (const float*)d_in[0];  // (161,161,128)
    const float* probs  = (const float*)d_in[1];  // (128,134)
    if (n_in >= 2 && in_sizes[0] < in_sizes[1]) { // safety: order by size
        const float* t = logits; logits = probs; probs = t;
    }
    float* out = (float*)d_out;

    static int grid = 0;
    if (!grid) {
        cudaFuncSetAttribute(fused_kernel,
                             cudaFuncAttributePreferredSharedMemoryCarveout, 100);
        int occ = 0;
        cudaOccupancyMaxActiveBlocksPerMultiprocessor(&occ, fused_kernel, TPB, 0);
        if (occ < 1) occ = 1;
        int sm = 148;
        cudaDeviceGetAttribute(&sm, cudaDevAttrMultiProcessorCount, 0);
        grid = occ * sm;
        if (grid > NITEMS) grid = NITEMS;
    }

    fused_kernel<<<grid, TPB>>>(logits, probs, out);
}